// round 8
// baseline (speedup 1.0000x reference)
#include <cuda_runtime.h>
#include <cuda_bf16.h>
#include <cstdint>

// ChamferLoss B=4, N=8192, D=3.  (build r8: PPT=16)
// dist(n,m) = |q_n|^2 + (|g_m|^2 - 2 q_n . g_m). Inner loop computes
// s = g2 - 2 q.g with packed fma.rn.f32x2 (2 query points per op); |q|^2 is
// added after the min. Refs staged in shared pre-duplicated:
//   (-2gx,-2gx)(-2gy,-2gy) | (-2gz,-2gz)(g2,g2)
// so two LDS.128 yield ready-to-use packed operands for 16 query points.
//
// PPT=16: per ref-iter 24 FFMA2 = 48 fma-pipe cycles vs ~43 issue slots
// (16 FMNMX on alu pipe = 32 cycles, non-binding) -> fma pipe binds.
// 8 independent FMA chains/iter give ILP to cover latency at low occupancy.
//
// Decomposition: 4 batches x 2 dirs x 4 query-tiles(2048) x 32 ref-splits(256)
// = 1024 uniform blocks. Partial mins -> __device__ scratch; kernel2 combines
// mins + |q|^2 + weights + block-reduce; kernel3 final fixed-order sum.
// Deterministic, allocation-free, graph-capturable.

constexpr int B = 4;
constexpr int N = 8192;
constexpr int BLOCK = 128;
constexpr int PPT = 16;                   // queries per thread (8 f32x2 pairs)
constexpr int NPAIR = PPT / 2;            // 8
constexpr int QPB = BLOCK * PPT;          // 2048 queries per block
constexpr int QT  = N / QPB;              // 4 query tiles
constexpr int RS  = 32;                   // ref splits
constexpr int REFS_PER_RS = N / RS;       // 256
constexpr int TS  = 256;                  // refs per shared tile (8 KB)
constexpr int GRID1 = B * 2 * QT * RS;    // 1024 blocks
constexpr int NBD = B * 2;

// pmin layout: [bd(8)][qt(4)][rs(32)][2048]; block bx = (bd*QT+qt)*RS+rs
__device__ float g_pmin[NBD * QT * RS * QPB];
__device__ float g_partial2[128];

__device__ __forceinline__ unsigned long long fma2(
    unsigned long long a, unsigned long long b, unsigned long long c)
{
    unsigned long long d;
    asm("fma.rn.f32x2 %0, %1, %2, %3;" : "=l"(d) : "l"(a), "l"(b), "l"(c));
    return d;
}

__device__ __forceinline__ unsigned long long pack2(float lo, float hi)
{
    unsigned long long d;
    asm("mov.b64 %0, {%1, %2};" : "=l"(d) : "f"(lo), "f"(hi));
    return d;
}

__device__ __forceinline__ void unpack2(unsigned long long v, float& lo, float& hi)
{
    asm("mov.b64 {%0, %1}, %2;" : "=f"(lo), "=f"(hi) : "l"(v));
}

__global__ __launch_bounds__(BLOCK) void chamfer_min_kernel(
    const float* __restrict__ pred,
    const float* __restrict__ gt)
{
    const int bx  = blockIdx.x;
    const int rs  = bx & (RS - 1);
    const int qt  = (bx >> 5) & (QT - 1);
    const int bd  = bx >> 7;
    const int dir = bd & 1;
    const int b   = bd >> 1;

    const float* __restrict__ Q = (dir ? gt   : pred) + (size_t)(b * N) * 3;
    const float* __restrict__ R = (dir ? pred : gt  ) + (size_t)(b * N) * 3;

    __shared__ unsigned long long sh[4 * TS];

    const int tid = threadIdx.x;
    const float INF = __int_as_float(0x7f800000);

    // Queries: qt*2048 + tid + k*128, k=0..15; pair pp packs (k=2pp, 2pp+1).
    unsigned long long qx[NPAIR], qy[NPAIR], qz[NPAIR];
#pragma unroll
    for (int pp = 0; pp < NPAIR; pp++) {
        const int qa = qt * QPB + tid + (2 * pp) * BLOCK;
        const int qb = qa + BLOCK;
        qx[pp] = pack2(Q[3 * qa + 0], Q[3 * qb + 0]);
        qy[pp] = pack2(Q[3 * qa + 1], Q[3 * qb + 1]);
        qz[pp] = pack2(Q[3 * qa + 2], Q[3 * qb + 2]);
    }

    float mn[PPT];
#pragma unroll
    for (int k = 0; k < PPT; k++) mn[k] = INF;

    // Stage this block's ref split (256 refs = exactly one shared tile).
    const int t0 = rs * REFS_PER_RS;
    for (int j = tid; j < TS; j += BLOCK) {
        const float* rp = R + 3 * (t0 + j);
        const float gx = rp[0];
        const float gy = rp[1];
        const float gz = rp[2];
        const float g2 = fmaf(gx, gx, fmaf(gy, gy, gz * gz));
        unsigned long long* sp = sh + 4 * j;
        sp[0] = pack2(-2.0f * gx, -2.0f * gx);
        sp[1] = pack2(-2.0f * gy, -2.0f * gy);
        sp[2] = pack2(-2.0f * gz, -2.0f * gz);
        sp[3] = pack2(g2, g2);
    }
    __syncthreads();

    const ulonglong2* __restrict__ sh2 = reinterpret_cast<const ulonglong2*>(sh);
#pragma unroll 4
    for (int j = 0; j < TS; j++) {
        const ulonglong2 hxy = sh2[2 * j];      // (hxx, hyy)
        const ulonglong2 hzw = sh2[2 * j + 1];  // (hzz, hww)

        unsigned long long s[NPAIR];
#pragma unroll
        for (int pp = 0; pp < NPAIR; pp++) s[pp] = fma2(qx[pp], hxy.x, hzw.y);
#pragma unroll
        for (int pp = 0; pp < NPAIR; pp++) s[pp] = fma2(qy[pp], hxy.y, s[pp]);
#pragma unroll
        for (int pp = 0; pp < NPAIR; pp++) s[pp] = fma2(qz[pp], hzw.x, s[pp]);

#pragma unroll
        for (int pp = 0; pp < NPAIR; pp++) {
            float lo, hi;
            unpack2(s[pp], lo, hi);
            mn[2 * pp]     = fminf(mn[2 * pp], lo);
            mn[2 * pp + 1] = fminf(mn[2 * pp + 1], hi);
        }
    }

    float* __restrict__ out = g_pmin + (size_t)bx * QPB;
#pragma unroll
    for (int k = 0; k < PPT; k++)
        out[tid + k * BLOCK] = mn[k];
}

// kernel2: 128 blocks x 256 threads over (b,n); combine ref-split mins,
// add |q|^2 for both directions, weight, block-reduce.
__global__ __launch_bounds__(256) void chamfer_combine_kernel(
    const float* __restrict__ pred,
    const float* __restrict__ gt,
    const float* __restrict__ weight)
{
    const int i  = blockIdx.x * 256 + threadIdx.x;   // 0..32767
    const int b  = i >> 13;
    const int n  = i & (N - 1);
    const int qt = n >> 11;            // n / QPB
    const int ql = n & (QPB - 1);
    const float INF = __int_as_float(0x7f800000);

    const int base0 = ((b * 2 + 0) * QT + qt) * (RS * QPB) + ql;
    const int base1 = ((b * 2 + 1) * QT + qt) * (RS * QPB) + ql;
    float m0 = INF, m1 = INF;
#pragma unroll
    for (int r = 0; r < RS; r++) {
        m0 = fminf(m0, g_pmin[base0 + r * QPB]);
        m1 = fminf(m1, g_pmin[base1 + r * QPB]);
    }

    const float* P = pred   + (size_t)(b * N + n) * 3;
    const float* G = gt     + (size_t)(b * N + n) * 3;
    const float* W = weight + (size_t)(b * N + n) * 3;
    const float p2p = P[0] * P[0] + P[1] * P[1] + P[2] * P[2];
    const float p2g = G[0] * G[0] + G[1] * G[1] + G[2] * G[2];
    const float w   = (W[0] + W[1] + W[2]) * (1.0f / 3.0f);

    const float v = ((p2p + m0) + (p2g + m1)) * w;

    __shared__ float red[256];
    red[threadIdx.x] = v;
    __syncthreads();
#pragma unroll
    for (int s = 128; s > 0; s >>= 1) {
        if (threadIdx.x < s) red[threadIdx.x] += red[threadIdx.x + s];
        __syncthreads();
    }
    if (threadIdx.x == 0) g_partial2[blockIdx.x] = red[0];
}

__global__ void chamfer_final_kernel(float* __restrict__ out)
{
    __shared__ float red[128];
    const int tid = threadIdx.x;
    red[tid] = g_partial2[tid];
    __syncthreads();
#pragma unroll
    for (int s = 64; s > 0; s >>= 1) {
        if (tid < s) red[tid] += red[tid + s];
        __syncthreads();
    }
    if (tid == 0) out[0] = red[0] * (1.0f / (float)(B * N));
}

extern "C" void kernel_launch(void* const* d_in, const int* in_sizes, int n_in,
                              void* d_out, int out_size)
{
    const float* pred   = (const float*)d_in[0];
    const float* gt     = (const float*)d_in[1];
    const float* weight = (const float*)d_in[2];
    float* out = (float*)d_out;

    chamfer_min_kernel<<<GRID1, BLOCK>>>(pred, gt);
    chamfer_combine_kernel<<<128, 256>>>(pred, gt, weight);
    chamfer_final_kernel<<<1, 128>>>(out);
}

// round 9
// speedup vs baseline: 1.1112x; 1.1112x over previous
#include <cuda_runtime.h>
#include <cuda_bf16.h>
#include <cstdint>

// ChamferLoss B=4, N=8192, D=3.  (build r9: PPT=8, GRID=2048)
// dist(n,m) = |q_n|^2 + (|g_m|^2 - 2 q_n . g_m). Inner loop computes
// s = g2 - 2 q.g with packed fma.rn.f32x2 (2 query points per op); |q|^2 is
// added after the min. Refs staged in shared pre-duplicated:
//   (-2gx,-2gx)(-2gy,-2gy) | (-2gz,-2gz)(g2,g2)
// so two LDS.128 yield ready-to-use packed operands for 8 query points.
//
// R8 lesson: the binding constraint is exposed FMA latency at grid-limited
// occupancy (1024 blocks -> 28 warps/SM). This build keeps PPT=8 (best
// per-warp shape, 4 independent FMA chains) and doubles the grid to 2048
// blocks via RS=32 -> 36 warps/SM (reg-limited) ~= 56% occupancy.
//
// Decomposition: 4 batches x 2 dirs x 8 query-tiles(1024) x 32 ref-splits(256)
// = 2048 uniform blocks. Partial mins -> __device__ scratch; kernel2 combines
// mins + |q|^2 + weights + block-reduce; kernel3 final fixed-order sum.
// Deterministic, allocation-free, graph-capturable.

constexpr int B = 4;
constexpr int N = 8192;
constexpr int BLOCK = 128;
constexpr int PPT = 8;                    // queries per thread (4 f32x2 pairs)
constexpr int NPAIR = PPT / 2;            // 4
constexpr int QPB = BLOCK * PPT;          // 1024 queries per block
constexpr int QT  = N / QPB;              // 8 query tiles
constexpr int RS  = 32;                   // ref splits
constexpr int REFS_PER_RS = N / RS;       // 256
constexpr int TS  = 256;                  // refs per shared tile (8 KB)
constexpr int GRID1 = B * 2 * QT * RS;    // 2048 blocks
constexpr int NBD = B * 2;

// pmin layout: [bd(8)][qt(8)][rs(32)][1024]; block bx = (bd*QT+qt)*RS+rs
__device__ float g_pmin[NBD * QT * RS * QPB];
__device__ float g_partial2[128];

__device__ __forceinline__ unsigned long long fma2(
    unsigned long long a, unsigned long long b, unsigned long long c)
{
    unsigned long long d;
    asm("fma.rn.f32x2 %0, %1, %2, %3;" : "=l"(d) : "l"(a), "l"(b), "l"(c));
    return d;
}

__device__ __forceinline__ unsigned long long pack2(float lo, float hi)
{
    unsigned long long d;
    asm("mov.b64 %0, {%1, %2};" : "=l"(d) : "f"(lo), "f"(hi));
    return d;
}

__device__ __forceinline__ void unpack2(unsigned long long v, float& lo, float& hi)
{
    asm("mov.b64 {%0, %1}, %2;" : "=f"(lo), "=f"(hi) : "l"(v));
}

__global__ __launch_bounds__(BLOCK) void chamfer_min_kernel(
    const float* __restrict__ pred,
    const float* __restrict__ gt)
{
    const int bx  = blockIdx.x;
    const int rs  = bx & (RS - 1);
    const int qt  = (bx >> 5) & (QT - 1);
    const int bd  = bx >> 8;
    const int dir = bd & 1;
    const int b   = bd >> 1;

    const float* __restrict__ Q = (dir ? gt   : pred) + (size_t)(b * N) * 3;
    const float* __restrict__ R = (dir ? pred : gt  ) + (size_t)(b * N) * 3;

    __shared__ unsigned long long sh[4 * TS];

    const int tid = threadIdx.x;
    const float INF = __int_as_float(0x7f800000);

    // Queries: qt*1024 + tid + k*128, k=0..7; pair pp packs (k=2pp, k=2pp+1).
    unsigned long long qx[NPAIR], qy[NPAIR], qz[NPAIR];
#pragma unroll
    for (int pp = 0; pp < NPAIR; pp++) {
        const int qa = qt * QPB + tid + (2 * pp) * BLOCK;
        const int qb = qa + BLOCK;
        qx[pp] = pack2(Q[3 * qa + 0], Q[3 * qb + 0]);
        qy[pp] = pack2(Q[3 * qa + 1], Q[3 * qb + 1]);
        qz[pp] = pack2(Q[3 * qa + 2], Q[3 * qb + 2]);
    }

    float mn[PPT];
#pragma unroll
    for (int k = 0; k < PPT; k++) mn[k] = INF;

    // Stage this block's ref split (256 refs = exactly one shared tile).
    const int t0 = rs * REFS_PER_RS;
    for (int j = tid; j < TS; j += BLOCK) {
        const float* rp = R + 3 * (t0 + j);
        const float gx = rp[0];
        const float gy = rp[1];
        const float gz = rp[2];
        const float g2 = fmaf(gx, gx, fmaf(gy, gy, gz * gz));
        unsigned long long* sp = sh + 4 * j;
        sp[0] = pack2(-2.0f * gx, -2.0f * gx);
        sp[1] = pack2(-2.0f * gy, -2.0f * gy);
        sp[2] = pack2(-2.0f * gz, -2.0f * gz);
        sp[3] = pack2(g2, g2);
    }
    __syncthreads();

    const ulonglong2* __restrict__ sh2 = reinterpret_cast<const ulonglong2*>(sh);
#pragma unroll 8
    for (int j = 0; j < TS; j++) {
        const ulonglong2 hxy = sh2[2 * j];      // (hxx, hyy)
        const ulonglong2 hzw = sh2[2 * j + 1];  // (hzz, hww)

        unsigned long long s[NPAIR];
#pragma unroll
        for (int pp = 0; pp < NPAIR; pp++) s[pp] = fma2(qx[pp], hxy.x, hzw.y);
#pragma unroll
        for (int pp = 0; pp < NPAIR; pp++) s[pp] = fma2(qy[pp], hxy.y, s[pp]);
#pragma unroll
        for (int pp = 0; pp < NPAIR; pp++) s[pp] = fma2(qz[pp], hzw.x, s[pp]);

#pragma unroll
        for (int pp = 0; pp < NPAIR; pp++) {
            float lo, hi;
            unpack2(s[pp], lo, hi);
            mn[2 * pp]     = fminf(mn[2 * pp], lo);
            mn[2 * pp + 1] = fminf(mn[2 * pp + 1], hi);
        }
    }

    float* __restrict__ out = g_pmin + (size_t)bx * QPB;
#pragma unroll
    for (int k = 0; k < PPT; k++)
        out[tid + k * BLOCK] = mn[k];
}

// kernel2: 128 blocks x 256 threads over (b,n); combine ref-split mins,
// add |q|^2 for both directions, weight, block-reduce.
__global__ __launch_bounds__(256) void chamfer_combine_kernel(
    const float* __restrict__ pred,
    const float* __restrict__ gt,
    const float* __restrict__ weight)
{
    const int i  = blockIdx.x * 256 + threadIdx.x;   // 0..32767
    const int b  = i >> 13;
    const int n  = i & (N - 1);
    const int qt = n >> 10;            // n / QPB
    const int ql = n & (QPB - 1);
    const float INF = __int_as_float(0x7f800000);

    const int base0 = ((b * 2 + 0) * QT + qt) * (RS * QPB) + ql;
    const int base1 = ((b * 2 + 1) * QT + qt) * (RS * QPB) + ql;
    float m0 = INF, m1 = INF;
#pragma unroll
    for (int r = 0; r < RS; r++) {
        m0 = fminf(m0, g_pmin[base0 + r * QPB]);
        m1 = fminf(m1, g_pmin[base1 + r * QPB]);
    }

    const float* P = pred   + (size_t)(b * N + n) * 3;
    const float* G = gt     + (size_t)(b * N + n) * 3;
    const float* W = weight + (size_t)(b * N + n) * 3;
    const float p2p = P[0] * P[0] + P[1] * P[1] + P[2] * P[2];
    const float p2g = G[0] * G[0] + G[1] * G[1] + G[2] * G[2];
    const float w   = (W[0] + W[1] + W[2]) * (1.0f / 3.0f);

    const float v = ((p2p + m0) + (p2g + m1)) * w;

    __shared__ float red[256];
    red[threadIdx.x] = v;
    __syncthreads();
#pragma unroll
    for (int s = 128; s > 0; s >>= 1) {
        if (threadIdx.x < s) red[threadIdx.x] += red[threadIdx.x + s];
        __syncthreads();
    }
    if (threadIdx.x == 0) g_partial2[blockIdx.x] = red[0];
}

__global__ void chamfer_final_kernel(float* __restrict__ out)
{
    __shared__ float red[128];
    const int tid = threadIdx.x;
    red[tid] = g_partial2[tid];
    __syncthreads();
#pragma unroll
    for (int s = 64; s > 0; s >>= 1) {
        if (tid < s) red[tid] += red[tid + s];
        __syncthreads();
    }
    if (tid == 0) out[0] = red[0] * (1.0f / (float)(B * N));
}

extern "C" void kernel_launch(void* const* d_in, const int* in_sizes, int n_in,
                              void* d_out, int out_size)
{
    const float* pred   = (const float*)d_in[0];
    const float* gt     = (const float*)d_in[1];
    const float* weight = (const float*)d_in[2];
    float* out = (float*)d_out;

    chamfer_min_kernel<<<GRID1, BLOCK>>>(pred, gt);
    chamfer_combine_kernel<<<128, 256>>>(pred, gt, weight);
    chamfer_final_kernel<<<1, 128>>>(out);
}

// round 12
// speedup vs baseline: 1.2071x; 1.0864x over previous
#include <cuda_runtime.h>
#include <cuda_bf16.h>
#include <cstdint>

// ChamferLoss B=4, N=8192, D=3.  (build r12 = ref-packed f32x2, 3rd submit)
//
// dist(n,m) = |q_n|^2 + (|g_m|^2 - 2 q_n . g_m). REF-side f32x2 packing:
// shared holds ref-pairs (x0,x1)(y0,y1)(z0,z1)(g2_0,g2_1) pre-scaled by -2;
// two LDS.128 give packed operands for 2 refs with zero duplication waste.
// Queries are duplicated into (q,q) register pairs once at setup (free:
// mov.b64 pack/unpack is register aliasing, no SASS).
// Separate even/odd-ref min accumulators shorten FMNMX chains.
//
// Measured basis (R9): issue ~56% invariant to occupancy -> FFMA2 operand
// collector (3 distinct 64-bit operands, structural rt=3) saturates. This
// build trims non-FFMA2 issue overhead (~3.25 -> ~2.9 issues/pair) and
// halves the end-tail via GRID=4096 uniform blocks.
//
// Decomposition: 4 batches x 2 dirs x 16 query-tiles(512) x 32 ref-splits(256)
// = 4096 blocks. Partial mins -> __device__ scratch; kernel2 combines mins +
// |q|^2 + weights + block-reduce; kernel3 final fixed-order sum.
// Deterministic, allocation-free, graph-capturable.

constexpr int B = 4;
constexpr int N = 8192;
constexpr int BLOCK = 128;
constexpr int PPT = 4;                    // queries per thread (dup'd packs)
constexpr int QPB = BLOCK * PPT;          // 512 queries per block
constexpr int QT  = N / QPB;              // 16 query tiles
constexpr int RS  = 32;                   // ref splits
constexpr int REFS_PER_RS = N / RS;       // 256
constexpr int TS  = 256;                  // refs per shared tile (4 KB)
constexpr int NPT = TS / 2;               // 128 ref-pairs per tile
constexpr int GRID1 = B * 2 * QT * RS;    // 4096 blocks
constexpr int NBD = B * 2;

// pmin layout: [bd(8)][qt(16)][rs(32)][512]; block bx = (bd*QT+qt)*RS+rs
__device__ float g_pmin[NBD * QT * RS * QPB];
__device__ float g_partial2[128];

__device__ __forceinline__ unsigned long long fma2(
    unsigned long long a, unsigned long long b, unsigned long long c)
{
    unsigned long long d;
    asm("fma.rn.f32x2 %0, %1, %2, %3;" : "=l"(d) : "l"(a), "l"(b), "l"(c));
    return d;
}

__device__ __forceinline__ unsigned long long pack2(float lo, float hi)
{
    unsigned long long d;
    asm("mov.b64 %0, {%1, %2};" : "=l"(d) : "f"(lo), "f"(hi));
    return d;
}

__device__ __forceinline__ void unpack2(unsigned long long v, float& lo, float& hi)
{
    asm("mov.b64 {%0, %1}, %2;" : "=f"(lo), "=f"(hi) : "l"(v));
}

__global__ __launch_bounds__(BLOCK) void chamfer_min_kernel(
    const float* __restrict__ pred,
    const float* __restrict__ gt)
{
    const int bx  = blockIdx.x;
    const int rs  = bx & (RS - 1);
    const int qt  = (bx >> 5) & (QT - 1);
    const int bd  = bx >> 9;
    const int dir = bd & 1;
    const int b   = bd >> 1;

    const float* __restrict__ Q = (dir ? gt   : pred) + (size_t)(b * N) * 3;
    const float* __restrict__ R = (dir ? pred : gt  ) + (size_t)(b * N) * 3;

    // Ref-pair jp: sh[4jp+0]=(-2x0,-2x1)  sh[4jp+1]=(-2y0,-2y1)
    //              sh[4jp+2]=(-2z0,-2z1)  sh[4jp+3]=(g2_0,g2_1)
    __shared__ unsigned long long sh[4 * NPT];

    const int tid = threadIdx.x;
    const float INF = __int_as_float(0x7f800000);

    // Queries: qt*512 + tid + k*128, k=0..3, duplicated into (q,q) packs.
    unsigned long long qxd[PPT], qyd[PPT], qzd[PPT];
#pragma unroll
    for (int k = 0; k < PPT; k++) {
        const int qi = qt * QPB + tid + k * BLOCK;
        const float x = Q[3 * qi + 0];
        const float y = Q[3 * qi + 1];
        const float z = Q[3 * qi + 2];
        qxd[k] = pack2(x, x);
        qyd[k] = pack2(y, y);
        qzd[k] = pack2(z, z);
    }

    float mnA[PPT], mnB[PPT];
#pragma unroll
    for (int k = 0; k < PPT; k++) { mnA[k] = INF; mnB[k] = INF; }

    // Stage: thread tid owns ref-pair tid (refs t0+2tid, t0+2tid+1).
    {
        const int t0 = rs * REFS_PER_RS;
        const float* rp = R + 3 * (t0 + 2 * tid);
        const float x0 = rp[0], y0 = rp[1], z0 = rp[2];
        const float x1 = rp[3], y1 = rp[4], z1 = rp[5];
        const float g20 = fmaf(x0, x0, fmaf(y0, y0, z0 * z0));
        const float g21 = fmaf(x1, x1, fmaf(y1, y1, z1 * z1));
        unsigned long long* sp = &sh[4 * tid];
        sp[0] = pack2(-2.0f * x0, -2.0f * x1);
        sp[1] = pack2(-2.0f * y0, -2.0f * y1);
        sp[2] = pack2(-2.0f * z0, -2.0f * z1);
        sp[3] = pack2(g20, g21);
    }
    __syncthreads();

    const ulonglong2* __restrict__ sh2 = reinterpret_cast<const ulonglong2*>(sh);
#pragma unroll 8
    for (int jp = 0; jp < NPT; jp++) {
        const ulonglong2 hxy = sh2[2 * jp];      // (xx pair, yy pair)
        const ulonglong2 hzw = sh2[2 * jp + 1];  // (zz pair, g2 pair)

        unsigned long long s[PPT];
#pragma unroll
        for (int k = 0; k < PPT; k++) s[k] = fma2(qxd[k], hxy.x, hzw.y);
#pragma unroll
        for (int k = 0; k < PPT; k++) s[k] = fma2(qyd[k], hxy.y, s[k]);
#pragma unroll
        for (int k = 0; k < PPT; k++) s[k] = fma2(qzd[k], hzw.x, s[k]);

#pragma unroll
        for (int k = 0; k < PPT; k++) {
            float lo, hi;
            unpack2(s[k], lo, hi);
            mnA[k] = fminf(mnA[k], lo);   // even refs
            mnB[k] = fminf(mnB[k], hi);   // odd refs
        }
    }

    float* __restrict__ out = g_pmin + (size_t)bx * QPB;
#pragma unroll
    for (int k = 0; k < PPT; k++)
        out[tid + k * BLOCK] = fminf(mnA[k], mnB[k]);
}

// kernel2: 128 blocks x 256 threads over (b,n); combine ref-split mins,
// add |q|^2 for both directions, weight, block-reduce.
__global__ __launch_bounds__(256) void chamfer_combine_kernel(
    const float* __restrict__ pred,
    const float* __restrict__ gt,
    const float* __restrict__ weight)
{
    const int i  = blockIdx.x * 256 + threadIdx.x;   // 0..32767
    const int b  = i >> 13;
    const int n  = i & (N - 1);
    const int qt = n >> 9;             // n / QPB (QPB=512)
    const int ql = n & (QPB - 1);
    const float INF = __int_as_float(0x7f800000);

    const int base0 = ((b * 2 + 0) * QT + qt) * (RS * QPB) + ql;
    const int base1 = ((b * 2 + 1) * QT + qt) * (RS * QPB) + ql;
    float m0 = INF, m1 = INF;
#pragma unroll
    for (int r = 0; r < RS; r++) {
        m0 = fminf(m0, g_pmin[base0 + r * QPB]);
        m1 = fminf(m1, g_pmin[base1 + r * QPB]);
    }

    const float* P = pred   + (size_t)(b * N + n) * 3;
    const float* G = gt     + (size_t)(b * N + n) * 3;
    const float* W = weight + (size_t)(b * N + n) * 3;
    const float p2p = P[0] * P[0] + P[1] * P[1] + P[2] * P[2];
    const float p2g = G[0] * G[0] + G[1] * G[1] + G[2] * G[2];
    const float w   = (W[0] + W[1] + W[2]) * (1.0f / 3.0f);

    const float v = ((p2p + m0) + (p2g + m1)) * w;

    __shared__ float red[256];
    red[threadIdx.x] = v;
    __syncthreads();
#pragma unroll
    for (int s = 128; s > 0; s >>= 1) {
        if (threadIdx.x < s) red[threadIdx.x] += red[threadIdx.x + s];
        __syncthreads();
    }
    if (threadIdx.x == 0) g_partial2[blockIdx.x] = red[0];
}

__global__ void chamfer_final_kernel(float* __restrict__ out)
{
    __shared__ float red[128];
    const int tid = threadIdx.x;
    red[tid] = g_partial2[tid];
    __syncthreads();
#pragma unroll
    for (int s = 64; s > 0; s >>= 1) {
        if (tid < s) red[tid] += red[tid + s];
        __syncthreads();
    }
    if (tid == 0) out[0] = red[0] * (1.0f / (float)(B * N));
}

extern "C" void kernel_launch(void* const* d_in, const int* in_sizes, int n_in,
                              void* d_out, int out_size)
{
    const float* pred   = (const float*)d_in[0];
    const float* gt     = (const float*)d_in[1];
    const float* weight = (const float*)d_in[2];
    float* out = (float*)d_out;

    chamfer_min_kernel<<<GRID1, BLOCK>>>(pred, gt);
    chamfer_combine_kernel<<<128, 256>>>(pred, gt, weight);
    chamfer_final_kernel<<<1, 128>>>(out);
}